// round 5
// baseline (speedup 1.0000x reference)
#include <cuda_runtime.h>
#include <cstdint>

// ---------------------------------------------------------------------------
// MoE MLP on legacy mma.sync (tf32 HMMA) — tcgen05 is unavailable because the
// harness compiles via compute_103 (non-'a') PTX, where tcgen05 is illegal.
//   GEMM1: C1[t, e*F+f] = tf32round( gelu( X @ W1[e] )[t,f] * probs[t,e] )
//   GEMM2: out[t,h]     = C1 @ W2_flat + residual[t,h]
// Pre-passes: round X to tf32 grid; transpose+round W1 -> [EF][H], W2 -> [H][EF]
// so both GEMMs stage A and B with pure cp.async (K-contiguous, no cvt in loop).
//
// R4 fix: g_c1 was passed to GEMM2 as a raw host-side __device__ symbol
// reference — on GB300 (ATS/pageableMemoryAccess=1) that dereferences host
// shadow memory silently (zeros), so out ≈ residual (rel_err 0.44). Resolve
// via cudaGetSymbolAddress like the other scratch buffers.
// ---------------------------------------------------------------------------

static constexpr int T_TOK = 2048;   // S*B
static constexpr int HID   = 1024;   // H
static constexpr int FFN   = 4096;   // F
static constexpr int NEXP  = 4;      // E
static constexpr int EF    = NEXP * FFN;  // 16384

// static device scratch (no allocation allowed)
__device__ float g_xr [(size_t)T_TOK * HID];     //   8 MB  rounded X
__device__ float g_w1t[(size_t)EF * HID];        //  67 MB  W1^T  [e*F+f][h]
__device__ float g_w2t[(size_t)HID * EF];        //  67 MB  W2^T  [h][e*F+f]
__device__ float g_c1 [(size_t)T_TOK * EF];      // 134 MB  intermediate

// ---------------------------------------------------------------------------
// helpers
// ---------------------------------------------------------------------------
__device__ __forceinline__ uint32_t smem_u32(const void* p) {
    uint32_t a;
    asm("{ .reg .u64 t; cvta.to.shared.u64 t, %1; cvt.u32.u64 %0, t; }"
        : "=r"(a) : "l"(p));
    return a;
}

__device__ __forceinline__ float to_tf32(float x) {
    uint32_t u;
    asm("cvt.rna.tf32.f32 %0, %1;" : "=r"(u) : "f"(x));
    return __uint_as_float(u);
}

__device__ __forceinline__ uint32_t sw128(uint32_t off) {
    return off ^ ((off >> 3) & 0x70);
}

__device__ __forceinline__ void cpa16(uint32_t dst, const void* src) {
    asm volatile("cp.async.cg.shared.global [%0], [%1], 16;"
                 :: "r"(dst), "l"(src) : "memory");
}

__device__ __forceinline__ void ldsm4(uint32_t* d, uint32_t addr) {
    asm volatile("ldmatrix.sync.aligned.m8n8.x4.shared.b16 {%0,%1,%2,%3}, [%4];"
                 : "=r"(d[0]), "=r"(d[1]), "=r"(d[2]), "=r"(d[3]) : "r"(addr));
}

__device__ __forceinline__ void mma8(float* c, const uint32_t* a,
                                     uint32_t b0, uint32_t b1) {
    asm volatile(
        "mma.sync.aligned.m16n8k8.row.col.f32.tf32.tf32.f32 "
        "{%0,%1,%2,%3}, {%4,%5,%6,%7}, {%8,%9}, {%0,%1,%2,%3};"
        : "+f"(c[0]), "+f"(c[1]), "+f"(c[2]), "+f"(c[3])
        : "r"(a[0]), "r"(a[1]), "r"(a[2]), "r"(a[3]), "r"(b0), "r"(b1));
}

__device__ __forceinline__ float gelu_exact(float x) {
    return 0.5f * x * (1.0f + erff(x * 0.70710678118654752f));
}

// ---------------------------------------------------------------------------
// pre-pass kernels
// ---------------------------------------------------------------------------
__global__ void round_tf32(const float* __restrict__ in, float* __restrict__ out,
                           int n4) {
    int i = blockIdx.x * 256 + threadIdx.x;
    if (i < n4) {
        float4 v = ((const float4*)in)[i];
        v.x = to_tf32(v.x); v.y = to_tf32(v.y);
        v.z = to_tf32(v.z); v.w = to_tf32(v.w);
        ((float4*)out)[i] = v;
    }
}

// in[b][r][c] -> out[b][c][r], rounded to tf32 grid. R,C multiples of 32.
__global__ void transpose_cvt(const float* __restrict__ in, float* __restrict__ out,
                              int R, int C) {
    __shared__ float tile[32][33];
    size_t base = (size_t)blockIdx.z * R * C;
    int c0 = blockIdx.x << 5, r0 = blockIdx.y << 5;
    int tx = threadIdx.x, ty = threadIdx.y;     // 32 x 8
    #pragma unroll
    for (int i = 0; i < 32; i += 8)
        tile[ty + i][tx] = to_tf32(in[base + (size_t)(r0 + ty + i) * C + c0 + tx]);
    __syncthreads();
    #pragma unroll
    for (int i = 0; i < 32; i += 8)
        out[base + (size_t)(c0 + ty + i) * R + r0 + tx] = tile[tx][ty + i];
}

// ---------------------------------------------------------------------------
// GEMM: C[128 x BN] tile per CTA, BK=32, 3-stage cp.async, 4 warps.
// Warp tile 64 x WN (warp grid 2m x 2n). A row-major [m][k], B = pre-transposed
// [n][k]; both staged K-contiguous into SW128-swizzled smem (128B rows).
// MODE 0: epilogue gelu*probs -> C1out (tf32-rounded). MODE 1: +residual -> out.
// ---------------------------------------------------------------------------
template<int BN, int WN, int MODE>
__global__ void __launch_bounds__(128, 2)
moe_gemm(const float* __restrict__ A,     // [M_total][K]  (g_xr or g_c1)
         const float* __restrict__ Bt,    // [N_total][K]  (g_w1t or g_w2t)
         const float* __restrict__ extra, // MODE0: probs [T,E]; MODE1: residual
         float* __restrict__ Cout,        // MODE0: g_c1;  MODE1: out
         int K)
{
    constexpr int A_BYTES = 128 * 128;    // 128 rows x 32 tf32
    constexpr int B_BYTES = BN * 128;
    constexpr int STAGE   = A_BYTES + B_BYTES;
    constexpr int NT      = WN / 8;       // n-tiles per warp

    extern __shared__ __align__(128) char smem[];
    const uint32_t sb = smem_u32(smem);

    const int tid  = threadIdx.x;
    const int wid  = tid >> 5;
    const int lane = tid & 31;
    const int wm   = wid >> 1;            // 0..1
    const int wn   = wid & 1;             // 0..1
    const int m0   = blockIdx.y * 128;
    const int n0   = blockIdx.x * BN;

    const float* Ap = A  + (size_t)m0 * K;
    const float* Bp = Bt + (size_t)n0 * K;

    const int CCH = K / 32;

    auto issue = [&](int c, int s) {
        uint32_t dA = sb + (uint32_t)s * STAGE;
        uint32_t dB = dA + A_BYTES;
        const float* As = Ap + c * 32;
        const float* Bs = Bp + c * 32;
        #pragma unroll
        for (int i = 0; i < 8; i++) {                 // A: 128 rows x 2 x 16B
            int idx = tid + i * 128;
            int row = idx >> 3, cb = (idx & 7) << 4;
            cpa16(dA + sw128((uint32_t)(row * 128 + cb)),
                  As + (size_t)row * K + (cb >> 2));
        }
        #pragma unroll
        for (int i = 0; i < BN / 16; i++) {           // B: BN rows
            int idx = tid + i * 128;
            int row = idx >> 3, cb = (idx & 7) << 4;
            cpa16(dB + sw128((uint32_t)(row * 128 + cb)),
                  Bs + (size_t)row * K + (cb >> 2));
        }
    };

    // prologue: stages 0,1
    issue(0, 0);
    asm volatile("cp.async.commit_group;" ::: "memory");
    issue(1, 1);
    asm volatile("cp.async.commit_group;" ::: "memory");

    float acc[4][NT][4];
    #pragma unroll
    for (int mt = 0; mt < 4; mt++)
        #pragma unroll
        for (int nt = 0; nt < NT; nt++)
            #pragma unroll
            for (int i = 0; i < 4; i++) acc[mt][nt][i] = 0.0f;

    const int g = lane >> 3, r = lane & 7;

    #pragma unroll 1
    for (int c = 0; c < CCH; c++) {
        asm volatile("cp.async.wait_group 1;" ::: "memory");
        __syncthreads();
        const int s = c % 3;
        const uint32_t sA = sb + (uint32_t)s * STAGE;
        const uint32_t sBm = sA + A_BYTES;

        #pragma unroll
        for (int ks = 0; ks < 4; ks++) {
            uint32_t af[4][4];
            uint32_t bf[NT * 2];
            #pragma unroll
            for (int mt = 0; mt < 4; mt++) {
                int arow = wm * 64 + mt * 16 + ((g & 1) << 3) + r;
                int acol = ks * 32 + ((g >> 1) << 4);
                ldsm4(af[mt], sA + sw128((uint32_t)(arow * 128 + acol)));
            }
            #pragma unroll
            for (int p = 0; p < NT / 2; p++) {
                int brow = wn * WN + p * 16 + ((g >> 1) << 3) + r;
                int bcol = ks * 32 + ((g & 1) << 4);
                ldsm4(&bf[4 * p], sBm + sw128((uint32_t)(brow * 128 + bcol)));
            }
            #pragma unroll
            for (int mt = 0; mt < 4; mt++)
                #pragma unroll
                for (int nt = 0; nt < NT; nt++)
                    mma8(acc[mt][nt], af[mt], bf[nt * 2], bf[nt * 2 + 1]);
        }

        if (c + 2 < CCH) issue(c + 2, (c + 2) % 3);
        asm volatile("cp.async.commit_group;" ::: "memory");
    }

    // ---------------- epilogue ----------------
    const int qr = lane >> 2, rm = lane & 3;
    const int e_idx = (MODE == 0) ? (n0 / FFN) : 0;   // BN=128 never crosses experts
    const int ldc = (MODE == 0) ? EF : HID;

    #pragma unroll
    for (int mt = 0; mt < 4; mt++) {
        const int row0 = m0 + wm * 64 + mt * 16 + qr;
        const int row1 = row0 + 8;
        float p0 = 1.0f, p1 = 1.0f;
        if (MODE == 0) {
            p0 = extra[row0 * NEXP + e_idx];
            p1 = extra[row1 * NEXP + e_idx];
        }
        #pragma unroll
        for (int nt = 0; nt < NT; nt++) {
            const int col = n0 + wn * WN + nt * 8 + (rm << 1);
            if (MODE == 0) {
                float2 v0, v1;
                v0.x = to_tf32(gelu_exact(acc[mt][nt][0]) * p0);
                v0.y = to_tf32(gelu_exact(acc[mt][nt][1]) * p0);
                v1.x = to_tf32(gelu_exact(acc[mt][nt][2]) * p1);
                v1.y = to_tf32(gelu_exact(acc[mt][nt][3]) * p1);
                *(float2*)&Cout[(size_t)row0 * ldc + col] = v0;
                *(float2*)&Cout[(size_t)row1 * ldc + col] = v1;
            } else {
                float2 r0v = *(const float2*)&extra[(size_t)row0 * HID + col];
                float2 r1v = *(const float2*)&extra[(size_t)row1 * HID + col];
                float2 v0, v1;
                v0.x = acc[mt][nt][0] + r0v.x;
                v0.y = acc[mt][nt][1] + r0v.y;
                v1.x = acc[mt][nt][2] + r1v.x;
                v1.y = acc[mt][nt][3] + r1v.y;
                *(float2*)&Cout[(size_t)row0 * ldc + col] = v0;
                *(float2*)&Cout[(size_t)row1 * ldc + col] = v1;
            }
        }
    }
}

// ---------------------------------------------------------------------------
// launch
// ---------------------------------------------------------------------------
extern "C" void kernel_launch(void* const* d_in, const int* in_sizes, int n_in,
                              void* d_out, int out_size) {
    const float* x     = (const float*)d_in[0];   // hidden_states [T,H]
    const float* resid = (const float*)d_in[1];   // mlp_residual  [T,H]
    const float* probs = (const float*)d_in[2];   // probs [T,E] (masked)
    // d_in[3] = routing_map (unused: probs already zero off top-k)
    const float* w1    = (const float*)d_in[4];   // [E,H,F]
    const float* w2    = (const float*)d_in[5];   // [E,F,H] = flat [EF,H]
    float* out = (float*)d_out;

    float *xr, *w1t, *w2t, *c1;
    cudaGetSymbolAddress((void**)&xr,  g_xr);
    cudaGetSymbolAddress((void**)&w1t, g_w1t);
    cudaGetSymbolAddress((void**)&w2t, g_w2t);
    cudaGetSymbolAddress((void**)&c1,  g_c1);     // R4 fix: device address!

    constexpr int SMEM1 = 3 * (128 * 128 + 128 * 128);   // 98304
    constexpr int SMEM2 = 3 * (128 * 128 +  64 * 128);   // 73728
    cudaFuncSetAttribute(moe_gemm<128, 64, 0>,
                         cudaFuncAttributeMaxDynamicSharedMemorySize, SMEM1);
    cudaFuncSetAttribute(moe_gemm<64, 32, 1>,
                         cudaFuncAttributeMaxDynamicSharedMemorySize, SMEM2);

    // pre-passes: round X; transpose+round W1 -> [EF][H], W2 -> [H][EF]
    round_tf32<<<(T_TOK * HID / 4 + 255) / 256, 256>>>(x, xr, T_TOK * HID / 4);
    transpose_cvt<<<dim3(FFN / 32, HID / 32, NEXP), dim3(32, 8)>>>(w1, w1t, HID, FFN);
    transpose_cvt<<<dim3(HID / 32, EF / 32, 1),    dim3(32, 8)>>>(w2, w2t, EF, HID);

    // GEMM1: [T,H] x [H,EF] -> c1 (gelu * probs), grid (128, 16)
    moe_gemm<128, 64, 0><<<dim3(EF / 128, T_TOK / 128), 128, SMEM1>>>(
        xr, w1t, probs, c1, HID);
    // GEMM2: [T,EF] x [EF,H] -> out (+residual),  grid (16, 16)
    moe_gemm<64, 32, 1><<<dim3(HID / 64, T_TOK / 128), 128, SMEM2>>>(
        c1, w2t, resid, out, EF);
}

// round 6
// speedup vs baseline: 1.8170x; 1.8170x over previous
#include <cuda_runtime.h>
#include <cstdint>

// ---------------------------------------------------------------------------
// MoE MLP, routed (top-k) formulation on legacy mma.sync tf32 HMMA
// (tcgen05 unavailable: harness compiles via non-'a' compute_103 PTX).
//
//   route:  per-expert compact token lists from probs>0 (TOPK=2 of E=4)
//   GEMM1:  a_e = gelu( X[list_e] @ W1[e] ) * probs[list_e,e]   (tf32-rounded)
//   GEMM2:  y_e = a_e @ W2[e]
//   combine: out[t] = resid[t] + sum_{e in topk(t)} y_e[slot(t,e)]
//
// Halves tensor FLOPs vs dense (137 -> 68.7 GF); GEMM1 was measured
// tensor-pipe-bound (67.4% busy), so time should scale ~linearly.
// ---------------------------------------------------------------------------

static constexpr int T_TOK = 2048;   // S*B
static constexpr int HID   = 1024;   // H
static constexpr int FFN   = 4096;   // F
static constexpr int NEXP  = 4;      // E
static constexpr int EF    = NEXP * FFN;  // 16384

// static device scratch (no allocation allowed)
__device__ float g_xr  [(size_t)T_TOK * HID];        //   8 MB rounded X
__device__ float g_w1t [(size_t)EF * HID];           //  67 MB W1^T [e*F+f][h]
__device__ float g_w2t [(size_t)HID * EF];           //  67 MB W2^T [h][e*F+f]
__device__ float g_c1p [(size_t)NEXP * T_TOK * FFN]; // 134 MB compact act
__device__ float g_y   [(size_t)NEXP * T_TOK * HID]; //  33 MB compact y
__device__ int   g_idx [NEXP * T_TOK];               // expert -> token list
__device__ int   g_slot[T_TOK * NEXP];               // (t,e) -> slot
__device__ int   g_cnt [NEXP];

// ---------------------------------------------------------------------------
// helpers
// ---------------------------------------------------------------------------
__device__ __forceinline__ uint32_t smem_u32(const void* p) {
    uint32_t a;
    asm("{ .reg .u64 t; cvta.to.shared.u64 t, %1; cvt.u32.u64 %0, t; }"
        : "=r"(a) : "l"(p));
    return a;
}

__device__ __forceinline__ float to_tf32(float x) {
    uint32_t u;
    asm("cvt.rna.tf32.f32 %0, %1;" : "=r"(u) : "f"(x));
    return __uint_as_float(u);
}

__device__ __forceinline__ uint32_t sw128(uint32_t off) {
    return off ^ ((off >> 3) & 0x70);
}

__device__ __forceinline__ void cpa16(uint32_t dst, const void* src) {
    asm volatile("cp.async.cg.shared.global [%0], [%1], 16;"
                 :: "r"(dst), "l"(src) : "memory");
}

__device__ __forceinline__ void ldsm4(uint32_t* d, uint32_t addr) {
    asm volatile("ldmatrix.sync.aligned.m8n8.x4.shared.b16 {%0,%1,%2,%3}, [%4];"
                 : "=r"(d[0]), "=r"(d[1]), "=r"(d[2]), "=r"(d[3]) : "r"(addr));
}

__device__ __forceinline__ void mma8(float* c, const uint32_t* a,
                                     uint32_t b0, uint32_t b1) {
    asm volatile(
        "mma.sync.aligned.m16n8k8.row.col.f32.tf32.tf32.f32 "
        "{%0,%1,%2,%3}, {%4,%5,%6,%7}, {%8,%9}, {%0,%1,%2,%3};"
        : "+f"(c[0]), "+f"(c[1]), "+f"(c[2]), "+f"(c[3])
        : "r"(a[0]), "r"(a[1]), "r"(a[2]), "r"(a[3]), "r"(b0), "r"(b1));
}

__device__ __forceinline__ float gelu_exact(float x) {
    return 0.5f * x * (1.0f + erff(x * 0.70710678118654752f));
}

// ---------------------------------------------------------------------------
// pre-pass kernels
// ---------------------------------------------------------------------------
__global__ void round_tf32(const float* __restrict__ in, float* __restrict__ out,
                           int n4) {
    int i = blockIdx.x * 256 + threadIdx.x;
    if (i < n4) {
        float4 v = ((const float4*)in)[i];
        v.x = to_tf32(v.x); v.y = to_tf32(v.y);
        v.z = to_tf32(v.z); v.w = to_tf32(v.w);
        ((float4*)out)[i] = v;
    }
}

// in[b][r][c] -> out[b][c][r], rounded. R,C multiples of 32.
__global__ void transpose_cvt(const float* __restrict__ in, float* __restrict__ out,
                              int R, int C) {
    __shared__ float tile[32][33];
    size_t base = (size_t)blockIdx.z * R * C;
    int c0 = blockIdx.x << 5, r0 = blockIdx.y << 5;
    int tx = threadIdx.x, ty = threadIdx.y;     // 32 x 8
    #pragma unroll
    for (int i = 0; i < 32; i += 8)
        tile[ty + i][tx] = to_tf32(in[base + (size_t)(r0 + ty + i) * C + c0 + tx]);
    __syncthreads();
    #pragma unroll
    for (int i = 0; i < 32; i += 8)
        out[base + (size_t)(c0 + ty + i) * R + r0 + tx] = tile[tx][ty + i];
}

// zero counters + index list (every launch: graph replay must be stateless)
__global__ void route_zero(int* idx, int* cnt) {
    int i = blockIdx.x * 256 + threadIdx.x;
    if (i < NEXP * T_TOK) idx[i] = 0;
    if (i < NEXP) cnt[i] = 0;
}

__global__ void route_build(const float* __restrict__ probs,
                            int* idx, int* slot, int* cnt) {
    int t = blockIdx.x * 256 + threadIdx.x;
    if (t >= T_TOK) return;
    #pragma unroll
    for (int e = 0; e < NEXP; e++) {
        if (probs[t * NEXP + e] > 0.0f) {
            int pos = atomicAdd(&cnt[e], 1);
            idx[e * T_TOK + pos] = t;
            slot[t * NEXP + e]  = pos;
        }
    }
}

// combine: out[t] = resid[t] + sum_e (probs>0) y[e][slot]
__global__ void combine(const float* __restrict__ y,
                        const float* __restrict__ probs,
                        const int* __restrict__ slot,
                        const float* __restrict__ resid,
                        float* __restrict__ out) {
    int t = blockIdx.x;
    int j = threadIdx.x;                          // 256 -> float4 over HID
    float4 acc = ((const float4*)resid)[t * (HID / 4) + j];
    #pragma unroll
    for (int e = 0; e < NEXP; e++) {
        if (probs[t * NEXP + e] > 0.0f) {
            int s = slot[t * NEXP + e];
            float4 v = ((const float4*)y)[((size_t)e * T_TOK + s) * (HID / 4) + j];
            acc.x += v.x; acc.y += v.y; acc.z += v.z; acc.w += v.w;
        }
    }
    ((float4*)out)[t * (HID / 4) + j] = acc;
}

// ---------------------------------------------------------------------------
// Routed GEMM: C[128 x 128] tile, BK=32, 3-stage cp.async, 4 warps (64x64 warp
// tile). gridDim.y = NEXP*16 (expert-major); CTAs past cnt[e] exit.
// MODE 0 (fc1): A rows gathered via token list; epi gelu*probs -> c1p (tf32).
// MODE 1 (fc2): A compact c1p rows; epi plain store -> y.
// ---------------------------------------------------------------------------
template<int MODE>
__global__ void __launch_bounds__(128, 2)
moe_gemm(const float* __restrict__ A,     // MODE0: g_xr [T,H]; MODE1: g_c1p
         const float* __restrict__ Bt,    // MODE0: g_w1t [EF][H]; MODE1: g_w2t [H][EF]
         const float* __restrict__ probs, // [T,E]
         const int* __restrict__ idx,
         const int* __restrict__ cnt,
         float* __restrict__ Cout,        // MODE0: g_c1p; MODE1: g_y
         int K)                           // MODE0: HID; MODE1: FFN
{
    constexpr int BN      = 128;
    constexpr int WN      = 64;
    constexpr int NT      = WN / 8;
    constexpr int A_BYTES = 128 * 128;
    constexpr int B_BYTES = BN * 128;
    constexpr int STAGE   = A_BYTES + B_BYTES;

    extern __shared__ __align__(128) char smem[];
    const uint32_t sb = smem_u32(smem);
    int* s_token = (int*)(smem + 3 * STAGE);

    const int e    = blockIdx.y >> 4;
    const int tile = blockIdx.y & 15;
    const int cnt_e = cnt[e];
    if (tile * 128 >= cnt_e) return;

    const int tid  = threadIdx.x;
    const int wid  = tid >> 5;
    const int lane = tid & 31;
    const int wm   = wid >> 1;
    const int wn   = wid & 1;
    const int n0   = blockIdx.x * BN;
    const int row_base = e * T_TOK + tile * 128;

    if (MODE == 0) {
        s_token[tid] = idx[row_base + tid];     // padded entries are 0 (valid)
        __syncthreads();
    }

    const int CCH = K / 32;

    auto issue = [&](int c, int s) {
        uint32_t dA = sb + (uint32_t)s * STAGE;
        uint32_t dB = dA + A_BYTES;
        const int k0 = c * 32;
        #pragma unroll
        for (int i = 0; i < 8; i++) {                 // A: 128 rows x 2 x 16B
            int id2 = tid + i * 128;
            int row = id2 >> 3, cb = (id2 & 7) << 4;
            const float* asrc;
            if (MODE == 0)
                asrc = A + (size_t)s_token[row] * K + k0 + (cb >> 2);
            else
                asrc = A + (size_t)(row_base + row) * K + k0 + (cb >> 2);
            cpa16(dA + sw128((uint32_t)(row * 128 + cb)), asrc);
        }
        #pragma unroll
        for (int i = 0; i < BN / 16; i++) {           // B: BN rows K-contig
            int id2 = tid + i * 128;
            int row = id2 >> 3, cb = (id2 & 7) << 4;
            const float* bsrc;
            if (MODE == 0)   // w1t rows e*F + n, stride K (=HID)
                bsrc = Bt + (size_t)(e * FFN + n0 + row) * K + k0 + (cb >> 2);
            else             // w2t rows n (stride EF), expert cols e*F + k
                bsrc = Bt + (size_t)(n0 + row) * EF + e * FFN + k0 + (cb >> 2);
            cpa16(dB + sw128((uint32_t)(row * 128 + cb)), bsrc);
        }
    };

    issue(0, 0);
    asm volatile("cp.async.commit_group;" ::: "memory");
    issue(1, 1);
    asm volatile("cp.async.commit_group;" ::: "memory");

    float acc[4][NT][4];
    #pragma unroll
    for (int mt = 0; mt < 4; mt++)
        #pragma unroll
        for (int nt = 0; nt < NT; nt++)
            #pragma unroll
            for (int i = 0; i < 4; i++) acc[mt][nt][i] = 0.0f;

    const int g = lane >> 3, r = lane & 7;

    #pragma unroll 1
    for (int c = 0; c < CCH; c++) {
        asm volatile("cp.async.wait_group 1;" ::: "memory");
        __syncthreads();
        const int s = c % 3;
        const uint32_t sA  = sb + (uint32_t)s * STAGE;
        const uint32_t sBm = sA + A_BYTES;

        #pragma unroll
        for (int ks = 0; ks < 4; ks++) {
            uint32_t af[4][4];
            uint32_t bf[NT * 2];
            #pragma unroll
            for (int mt = 0; mt < 4; mt++) {
                int arow = wm * 64 + mt * 16 + ((g & 1) << 3) + r;
                int acol = ks * 32 + ((g >> 1) << 4);
                ldsm4(af[mt], sA + sw128((uint32_t)(arow * 128 + acol)));
            }
            #pragma unroll
            for (int p = 0; p < NT / 2; p++) {
                int brow = wn * WN + p * 16 + ((g >> 1) << 3) + r;
                int bcol = ks * 32 + ((g & 1) << 4);
                ldsm4(&bf[4 * p], sBm + sw128((uint32_t)(brow * 128 + bcol)));
            }
            #pragma unroll
            for (int mt = 0; mt < 4; mt++)
                #pragma unroll
                for (int nt = 0; nt < NT; nt++)
                    mma8(acc[mt][nt], af[mt], bf[nt * 2], bf[nt * 2 + 1]);
        }

        if (c + 2 < CCH) issue(c + 2, (c + 2) % 3);
        asm volatile("cp.async.commit_group;" ::: "memory");
    }

    // ---------------- epilogue ----------------
    const int qr = lane >> 2, rm = lane & 3;
    const int ldc = (MODE == 0) ? FFN : HID;

    #pragma unroll
    for (int mt = 0; mt < 4; mt++) {
        const int lr0 = wm * 64 + mt * 16 + qr;       // local compact row
        const int lr1 = lr0 + 8;
        float p0 = 1.0f, p1 = 1.0f;
        if (MODE == 0) {
            p0 = probs[s_token[lr0] * NEXP + e];
            p1 = probs[s_token[lr1] * NEXP + e];
        }
        #pragma unroll
        for (int nt = 0; nt < NT; nt++) {
            const int col = n0 + wn * WN + nt * 8 + (rm << 1);
            float2 v0, v1;
            if (MODE == 0) {
                v0.x = to_tf32(gelu_exact(acc[mt][nt][0]) * p0);
                v0.y = to_tf32(gelu_exact(acc[mt][nt][1]) * p0);
                v1.x = to_tf32(gelu_exact(acc[mt][nt][2]) * p1);
                v1.y = to_tf32(gelu_exact(acc[mt][nt][3]) * p1);
            } else {
                v0.x = acc[mt][nt][0]; v0.y = acc[mt][nt][1];
                v1.x = acc[mt][nt][2]; v1.y = acc[mt][nt][3];
            }
            *(float2*)&Cout[(size_t)(row_base + lr0) * ldc + col] = v0;
            *(float2*)&Cout[(size_t)(row_base + lr1) * ldc + col] = v1;
        }
    }
}

// ---------------------------------------------------------------------------
// launch
// ---------------------------------------------------------------------------
extern "C" void kernel_launch(void* const* d_in, const int* in_sizes, int n_in,
                              void* d_out, int out_size) {
    const float* x     = (const float*)d_in[0];   // hidden_states [T,H]
    const float* resid = (const float*)d_in[1];   // mlp_residual  [T,H]
    const float* probs = (const float*)d_in[2];   // probs [T,E] (masked)
    // d_in[3] = routing_map (unused: probs>0 is the same mask, dtype-safe)
    const float* w1    = (const float*)d_in[4];   // [E,H,F]
    const float* w2    = (const float*)d_in[5];   // [E,F,H]
    float* out = (float*)d_out;

    float *xr, *w1t, *w2t, *c1p, *yp;
    int *idxp, *slotp, *cntp;
    cudaGetSymbolAddress((void**)&xr,   g_xr);
    cudaGetSymbolAddress((void**)&w1t,  g_w1t);
    cudaGetSymbolAddress((void**)&w2t,  g_w2t);
    cudaGetSymbolAddress((void**)&c1p,  g_c1p);
    cudaGetSymbolAddress((void**)&yp,   g_y);
    cudaGetSymbolAddress((void**)&idxp, g_idx);
    cudaGetSymbolAddress((void**)&slotp, g_slot);
    cudaGetSymbolAddress((void**)&cntp, g_cnt);

    constexpr int SMEM = 3 * (128 * 128 + 128 * 128) + 512;   // 98816
    cudaFuncSetAttribute(moe_gemm<0>,
                         cudaFuncAttributeMaxDynamicSharedMemorySize, SMEM);
    cudaFuncSetAttribute(moe_gemm<1>,
                         cudaFuncAttributeMaxDynamicSharedMemorySize, SMEM);

    // routing
    route_zero<<<(NEXP * T_TOK + 255) / 256, 256>>>(idxp, cntp);
    route_build<<<(T_TOK + 255) / 256, 256>>>(probs, idxp, slotp, cntp);

    // operand prep: round X; transpose+round W1 -> [EF][H], W2 -> [H][EF]
    round_tf32<<<(T_TOK * HID / 4 + 255) / 256, 256>>>(x, xr, T_TOK * HID / 4);
    transpose_cvt<<<dim3(FFN / 32, HID / 32, NEXP), dim3(32, 8)>>>(w1, w1t, HID, FFN);
    transpose_cvt<<<dim3(HID / 32, EF / 32, 1),    dim3(32, 8)>>>(w2, w2t, EF, HID);

    // routed GEMM1: gather X -> gelu*probs -> c1p.   grid (32, 64)
    moe_gemm<0><<<dim3(FFN / 128, NEXP * 16), 128, SMEM>>>(
        xr, w1t, probs, idxp, cntp, c1p, HID);
    // routed GEMM2: c1p @ W2[e] -> y.                grid (8, 64)
    moe_gemm<1><<<dim3(HID / 128, NEXP * 16), 128, SMEM>>>(
        c1p, w2t, probs, idxp, cntp, yp, FFN);
    // combine: out = resid + sum_topk y
    combine<<<T_TOK, 256>>>(yp, probs, slotp, resid, out);
}

// round 7
// speedup vs baseline: 1.9994x; 1.1004x over previous
#include <cuda_runtime.h>
#include <cstdint>

// ---------------------------------------------------------------------------
// MoE MLP, routed (top-k) formulation on legacy mma.sync tf32 HMMA
// (tcgen05 unavailable: harness compiles via non-'a' compute_103 PTX).
//
//   route:  per-expert compact token lists from probs>0 (TOPK=2 of E=4)
//   GEMM1:  a_e = gelu( X[list_e] @ W1[e] ) * probs[list_e,e]   (tf32-rounded)
//   GEMM2:  y_e = a_e @ W2[e]
//   combine: out[t] = resid[t] + sum_{e in topk(t)} y_e[slot(t,e)]
//
// R7: smem-crossbar analysis (tensor=67.4% == 512 MMA / 768 wavefronts) says
// the mainloop is wavefront-bound, not tensor-bound. Warp tile 64x64 -> 96x64
// (CTA 192x128, 2-stage pipeline) cuts wf/MMA 1.5 -> 1.25. Transpose prepass
// vectorized (float4 both sides).
// ---------------------------------------------------------------------------

static constexpr int T_TOK = 2048;   // S*B
static constexpr int HID   = 1024;   // H
static constexpr int FFN   = 4096;   // F
static constexpr int NEXP  = 4;      // E
static constexpr int EF    = NEXP * FFN;  // 16384

static constexpr int BM   = 192;                 // CTA tile M
static constexpr int MT_N = 11;                  // ceil(2048/192)
static constexpr int CAP  = BM * MT_N;           // 2112 rows per expert

// static device scratch (no allocation allowed)
__device__ float g_xr  [(size_t)T_TOK * HID];      //   8 MB rounded X
__device__ float g_w1t [(size_t)EF * HID];         //  67 MB W1^T [e*F+f][h]
__device__ float g_w2t [(size_t)HID * EF];         //  67 MB W2^T [h][e*F+f]
__device__ float g_c1p [(size_t)NEXP * CAP * FFN]; // 138 MB compact act
__device__ float g_y   [(size_t)NEXP * CAP * HID]; //  35 MB compact y
__device__ int   g_idx [NEXP * CAP];               // expert -> token list
__device__ int   g_slot[T_TOK * NEXP];             // (t,e) -> slot
__device__ int   g_cnt [NEXP];

// ---------------------------------------------------------------------------
// helpers
// ---------------------------------------------------------------------------
__device__ __forceinline__ uint32_t smem_u32(const void* p) {
    uint32_t a;
    asm("{ .reg .u64 t; cvta.to.shared.u64 t, %1; cvt.u32.u64 %0, t; }"
        : "=r"(a) : "l"(p));
    return a;
}

__device__ __forceinline__ float to_tf32(float x) {
    uint32_t u;
    asm("cvt.rna.tf32.f32 %0, %1;" : "=r"(u) : "f"(x));
    return __uint_as_float(u);
}

__device__ __forceinline__ uint32_t sw128(uint32_t off) {
    return off ^ ((off >> 3) & 0x70);
}

__device__ __forceinline__ void cpa16(uint32_t dst, const void* src) {
    asm volatile("cp.async.cg.shared.global [%0], [%1], 16;"
                 :: "r"(dst), "l"(src) : "memory");
}

__device__ __forceinline__ void ldsm4(uint32_t* d, uint32_t addr) {
    asm volatile("ldmatrix.sync.aligned.m8n8.x4.shared.b16 {%0,%1,%2,%3}, [%4];"
                 : "=r"(d[0]), "=r"(d[1]), "=r"(d[2]), "=r"(d[3]) : "r"(addr));
}

__device__ __forceinline__ void mma8(float* c, const uint32_t* a,
                                     uint32_t b0, uint32_t b1) {
    asm volatile(
        "mma.sync.aligned.m16n8k8.row.col.f32.tf32.tf32.f32 "
        "{%0,%1,%2,%3}, {%4,%5,%6,%7}, {%8,%9}, {%0,%1,%2,%3};"
        : "+f"(c[0]), "+f"(c[1]), "+f"(c[2]), "+f"(c[3])
        : "r"(a[0]), "r"(a[1]), "r"(a[2]), "r"(a[3]), "r"(b0), "r"(b1));
}

__device__ __forceinline__ float gelu_exact(float x) {
    return 0.5f * x * (1.0f + erff(x * 0.70710678118654752f));
}

// ---------------------------------------------------------------------------
// pre-pass kernels
// ---------------------------------------------------------------------------
__global__ void round_tf32(const float* __restrict__ in, float* __restrict__ out,
                           int n4) {
    int i = blockIdx.x * 256 + threadIdx.x;
    if (i < n4) {
        float4 v = ((const float4*)in)[i];
        v.x = to_tf32(v.x); v.y = to_tf32(v.y);
        v.z = to_tf32(v.z); v.w = to_tf32(v.w);
        ((float4*)out)[i] = v;
    }
}

// in[b][r][c] -> out[b][c][r], rounded. 64x64 tiles, float4 both gmem sides.
__global__ void transpose_cvt(const float* __restrict__ in, float* __restrict__ out,
                              int R, int C) {
    __shared__ float tile[64][68];                 // [c][r], pad 68 (16B-mult)
    size_t base = (size_t)blockIdx.z * R * C;
    int c0 = blockIdx.x << 6, r0 = blockIdx.y << 6;
    int tx = threadIdx.x, ty = threadIdx.y;        // 16 x 16
    #pragma unroll
    for (int i = 0; i < 4; i++) {
        int rr = ty + (i << 4);
        float4 v = *(const float4*)&in[base + (size_t)(r0 + rr) * C + c0 + (tx << 2)];
        tile[(tx << 2) + 0][rr] = to_tf32(v.x);
        tile[(tx << 2) + 1][rr] = to_tf32(v.y);
        tile[(tx << 2) + 2][rr] = to_tf32(v.z);
        tile[(tx << 2) + 3][rr] = to_tf32(v.w);
    }
    __syncthreads();
    #pragma unroll
    for (int i = 0; i < 4; i++) {
        int cc = ty + (i << 4);
        float4 w = *(const float4*)&tile[cc][tx << 2];
        *(float4*)&out[base + (size_t)(c0 + cc) * R + r0 + (tx << 2)] = w;
    }
}

// zero counters + index list (every launch: graph replay must be stateless)
__global__ void route_zero(int* idx, int* cnt) {
    int i = blockIdx.x * 256 + threadIdx.x;
    if (i < NEXP * CAP) idx[i] = 0;
    if (i < NEXP) cnt[i] = 0;
}

__global__ void route_build(const float* __restrict__ probs,
                            int* idx, int* slot, int* cnt) {
    int t = blockIdx.x * 256 + threadIdx.x;
    if (t >= T_TOK) return;
    #pragma unroll
    for (int e = 0; e < NEXP; e++) {
        if (probs[t * NEXP + e] > 0.0f) {
            int pos = atomicAdd(&cnt[e], 1);
            idx[e * CAP + pos] = t;
            slot[t * NEXP + e] = pos;
        }
    }
}

// combine: out[t] = resid[t] + sum_e (probs>0) y[e][slot]
__global__ void combine(const float* __restrict__ y,
                        const float* __restrict__ probs,
                        const int* __restrict__ slot,
                        const float* __restrict__ resid,
                        float* __restrict__ out) {
    int t = blockIdx.x;
    int j = threadIdx.x;                          // 256 -> float4 over HID
    float4 acc = ((const float4*)resid)[t * (HID / 4) + j];
    #pragma unroll
    for (int e = 0; e < NEXP; e++) {
        if (probs[t * NEXP + e] > 0.0f) {
            int s = slot[t * NEXP + e];
            float4 v = ((const float4*)y)[((size_t)e * CAP + s) * (HID / 4) + j];
            acc.x += v.x; acc.y += v.y; acc.z += v.z; acc.w += v.w;
        }
    }
    ((float4*)out)[t * (HID / 4) + j] = acc;
}

// ---------------------------------------------------------------------------
// Routed GEMM: CTA tile 192x128, warp tile 96x64 (2x2 warps), BK=32, 2-stage
// cp.async. gridDim.y = NEXP*MT_N (expert-major); CTAs past cnt[e] exit.
// MODE 0 (fc1): A rows gathered via token list; epi gelu*probs -> c1p (tf32).
// MODE 1 (fc2): A compact c1p rows; epi plain store -> y.
// ---------------------------------------------------------------------------
template<int MODE>
__global__ void __launch_bounds__(128, 2)
moe_gemm(const float* __restrict__ A,     // MODE0: g_xr [T,H]; MODE1: g_c1p
         const float* __restrict__ Bt,    // MODE0: g_w1t [EF][H]; MODE1: g_w2t [H][EF]
         const float* __restrict__ probs, // [T,E]
         const int* __restrict__ idx,
         const int* __restrict__ cnt,
         float* __restrict__ Cout,        // MODE0: g_c1p; MODE1: g_y
         int K)                           // MODE0: HID; MODE1: FFN
{
    constexpr int BN      = 128;
    constexpr int NT      = 8;            // 64-wide warp tile / 8
    constexpr int MT      = 6;            // 96-tall warp tile / 16
    constexpr int A_BYTES = BM * 128;     // 24576
    constexpr int B_BYTES = BN * 128;     // 16384
    constexpr int STAGE   = A_BYTES + B_BYTES;

    extern __shared__ __align__(128) char smem[];
    const uint32_t sb = smem_u32(smem);
    int* s_token = (int*)(smem + 2 * STAGE);

    const int e    = blockIdx.y / MT_N;
    const int tile = blockIdx.y % MT_N;
    const int cnt_e = cnt[e];
    if (tile * BM >= cnt_e) return;

    const int tid  = threadIdx.x;
    const int wid  = tid >> 5;
    const int lane = tid & 31;
    const int wm   = wid >> 1;
    const int wn   = wid & 1;
    const int n0   = blockIdx.x * BN;
    const int row_base = e * CAP + tile * BM;

    if (MODE == 0) {
        #pragma unroll
        for (int i = tid; i < BM; i += 128) s_token[i] = idx[row_base + i];
    }
    __syncthreads();

    const int CCH = K / 32;

    auto issue = [&](int c, int s) {
        uint32_t dA = sb + (uint32_t)s * STAGE;
        uint32_t dB = dA + A_BYTES;
        const int k0 = c * 32;
        #pragma unroll
        for (int i = 0; i < BM / 16; i++) {           // A: BM rows x 2 x 16B
            int id2 = tid + i * 128;
            int row = id2 >> 3, cb = (id2 & 7) << 4;
            const float* asrc;
            if (MODE == 0)
                asrc = A + (size_t)s_token[row] * K + k0 + (cb >> 2);
            else
                asrc = A + (size_t)(row_base + row) * K + k0 + (cb >> 2);
            cpa16(dA + sw128((uint32_t)(row * 128 + cb)), asrc);
        }
        #pragma unroll
        for (int i = 0; i < BN / 16; i++) {           // B: BN rows K-contig
            int id2 = tid + i * 128;
            int row = id2 >> 3, cb = (id2 & 7) << 4;
            const float* bsrc;
            if (MODE == 0)   // w1t rows e*F + n, stride K (=HID)
                bsrc = Bt + (size_t)(e * FFN + n0 + row) * K + k0 + (cb >> 2);
            else             // w2t rows n (stride EF), expert cols e*F + k
                bsrc = Bt + (size_t)(n0 + row) * EF + e * FFN + k0 + (cb >> 2);
            cpa16(dB + sw128((uint32_t)(row * 128 + cb)), bsrc);
        }
    };

    issue(0, 0);
    asm volatile("cp.async.commit_group;" ::: "memory");

    float acc[MT][NT][4];
    #pragma unroll
    for (int mt = 0; mt < MT; mt++)
        #pragma unroll
        for (int nt = 0; nt < NT; nt++)
            #pragma unroll
            for (int i = 0; i < 4; i++) acc[mt][nt][i] = 0.0f;

    const int g = lane >> 3, r = lane & 7;

    #pragma unroll 1
    for (int c = 0; c < CCH; c++) {
        // prefetch next chunk into the other buffer (prev compute done: bar below)
        if (c + 1 < CCH) {
            issue(c + 1, (c + 1) & 1);
            asm volatile("cp.async.commit_group;" ::: "memory");
            asm volatile("cp.async.wait_group 1;" ::: "memory");
        } else {
            asm volatile("cp.async.wait_group 0;" ::: "memory");
        }
        __syncthreads();

        const uint32_t sA  = sb + (uint32_t)(c & 1) * STAGE;
        const uint32_t sBm = sA + A_BYTES;

        #pragma unroll
        for (int ks = 0; ks < 4; ks++) {
            uint32_t bf[NT * 2];
            #pragma unroll
            for (int p = 0; p < NT / 2; p++) {
                int brow = wn * 64 + p * 16 + ((g >> 1) << 3) + r;
                int bcol = ks * 32 + ((g & 1) << 4);
                ldsm4(&bf[4 * p], sBm + sw128((uint32_t)(brow * 128 + bcol)));
            }
            uint32_t af[2][4];
            {
                int arow = wm * 96 + ((g & 1) << 3) + r;
                int acol = ks * 32 + ((g >> 1) << 4);
                ldsm4(af[0], sA + sw128((uint32_t)(arow * 128 + acol)));
            }
            #pragma unroll
            for (int mt = 0; mt < MT; mt++) {
                if (mt + 1 < MT) {
                    int arow = wm * 96 + (mt + 1) * 16 + ((g & 1) << 3) + r;
                    int acol = ks * 32 + ((g >> 1) << 4);
                    ldsm4(af[(mt + 1) & 1], sA + sw128((uint32_t)(arow * 128 + acol)));
                }
                #pragma unroll
                for (int nt = 0; nt < NT; nt++)
                    mma8(acc[mt][nt], af[mt & 1], bf[nt * 2], bf[nt * 2 + 1]);
            }
        }
        __syncthreads();   // all warps done with buffer c&1 before next issue
    }

    // ---------------- epilogue ----------------
    const int qr = lane >> 2, rm = lane & 3;
    const int ldc = (MODE == 0) ? FFN : HID;

    #pragma unroll
    for (int mt = 0; mt < MT; mt++) {
        const int lr0 = wm * 96 + mt * 16 + qr;       // local compact row
        const int lr1 = lr0 + 8;
        float p0 = 1.0f, p1 = 1.0f;
        if (MODE == 0) {
            p0 = probs[s_token[lr0] * NEXP + e];
            p1 = probs[s_token[lr1] * NEXP + e];
        }
        #pragma unroll
        for (int nt = 0; nt < NT; nt++) {
            const int col = n0 + wn * 64 + nt * 8 + (rm << 1);
            float2 v0, v1;
            if (MODE == 0) {
                v0.x = to_tf32(gelu_exact(acc[mt][nt][0]) * p0);
                v0.y = to_tf32(gelu_exact(acc[mt][nt][1]) * p0);
                v1.x = to_tf32(gelu_exact(acc[mt][nt][2]) * p1);
                v1.y = to_tf32(gelu_exact(acc[mt][nt][3]) * p1);
            } else {
                v0.x = acc[mt][nt][0]; v0.y = acc[mt][nt][1];
                v1.x = acc[mt][nt][2]; v1.y = acc[mt][nt][3];
            }
            *(float2*)&Cout[(size_t)(row_base + lr0) * ldc + col] = v0;
            *(float2*)&Cout[(size_t)(row_base + lr1) * ldc + col] = v1;
        }
    }
}

// ---------------------------------------------------------------------------
// launch
// ---------------------------------------------------------------------------
extern "C" void kernel_launch(void* const* d_in, const int* in_sizes, int n_in,
                              void* d_out, int out_size) {
    const float* x     = (const float*)d_in[0];   // hidden_states [T,H]
    const float* resid = (const float*)d_in[1];   // mlp_residual  [T,H]
    const float* probs = (const float*)d_in[2];   // probs [T,E] (masked)
    // d_in[3] = routing_map (unused: probs>0 is the same mask, dtype-safe)
    const float* w1    = (const float*)d_in[4];   // [E,H,F]
    const float* w2    = (const float*)d_in[5];   // [E,F,H]
    float* out = (float*)d_out;

    float *xr, *w1t, *w2t, *c1p, *yp;
    int *idxp, *slotp, *cntp;
    cudaGetSymbolAddress((void**)&xr,   g_xr);
    cudaGetSymbolAddress((void**)&w1t,  g_w1t);
    cudaGetSymbolAddress((void**)&w2t,  g_w2t);
    cudaGetSymbolAddress((void**)&c1p,  g_c1p);
    cudaGetSymbolAddress((void**)&yp,   g_y);
    cudaGetSymbolAddress((void**)&idxp, g_idx);
    cudaGetSymbolAddress((void**)&slotp, g_slot);
    cudaGetSymbolAddress((void**)&cntp, g_cnt);

    constexpr int SMEM = 2 * (BM * 128 + 128 * 128) + BM * 4;   // 82688
    cudaFuncSetAttribute(moe_gemm<0>,
                         cudaFuncAttributeMaxDynamicSharedMemorySize, SMEM);
    cudaFuncSetAttribute(moe_gemm<1>,
                         cudaFuncAttributeMaxDynamicSharedMemorySize, SMEM);

    // routing
    route_zero<<<(NEXP * CAP + 255) / 256, 256>>>(idxp, cntp);
    route_build<<<(T_TOK + 255) / 256, 256>>>(probs, idxp, slotp, cntp);

    // operand prep: round X; transpose+round W1 -> [EF][H], W2 -> [H][EF]
    round_tf32<<<(T_TOK * HID / 4 + 255) / 256, 256>>>(x, xr, T_TOK * HID / 4);
    transpose_cvt<<<dim3(FFN / 64, HID / 64, NEXP), dim3(16, 16)>>>(w1, w1t, HID, FFN);
    transpose_cvt<<<dim3(HID / 64, EF / 64, 1),    dim3(16, 16)>>>(w2, w2t, EF, HID);

    // routed GEMM1: gather X -> gelu*probs -> c1p.   grid (32, 44)
    moe_gemm<0><<<dim3(FFN / 128, NEXP * MT_N), 128, SMEM>>>(
        xr, w1t, probs, idxp, cntp, c1p, HID);
    // routed GEMM2: c1p @ W2[e] -> y.                grid (8, 44)
    moe_gemm<1><<<dim3(HID / 128, NEXP * MT_N), 128, SMEM>>>(
        c1p, w2t, probs, idxp, cntp, yp, FFN);
    // combine: out = resid + sum_topk y
    combine<<<T_TOK, 256>>>(yp, probs, slotp, resid, out);
}

// round 8
// speedup vs baseline: 2.1805x; 1.0906x over previous
#include <cuda_runtime.h>
#include <cstdint>

// ---------------------------------------------------------------------------
// MoE MLP, routed (top-k) formulation on legacy mma.sync tf32 HMMA
// (tcgen05 unavailable: harness compiles via non-'a' compute_103 PTX).
//
//   route:  per-expert compact token lists from probs>0 (TOPK=2 of E=4)
//   GEMM1:  a_e = gelu( X[list_e] @ W1[e] ) * probs[list_e,e]   (tf32-rounded)
//   GEMM2:  y_e = a_e @ W2[e]
//   combine: out[t] = resid[t] + sum_{e in topk(t)} y_e[slot(t,e)]
//
// R8: GEMM1 widened to 256-thread CTA 192x256 (warp 96x64, 2x4), 3-stage
// pipeline with one barrier per chunk (wf/MMA 1.25 -> 1.125). GEMM2 reshaped
// to 96x128 tiles, occupancy 3 (704 CTAs -> no wave-tail waste).
// ---------------------------------------------------------------------------

static constexpr int T_TOK = 2048;   // S*B
static constexpr int HID   = 1024;   // H
static constexpr int FFN   = 4096;   // F
static constexpr int NEXP  = 4;      // E
static constexpr int EF    = NEXP * FFN;  // 16384

static constexpr int CAP  = 2112;    // per-expert row capacity (192*11 = 96*22)

// static device scratch (no allocation allowed)
__device__ float g_xr  [(size_t)T_TOK * HID];      //   8 MB rounded X
__device__ float g_w1t [(size_t)EF * HID];         //  67 MB W1^T [e*F+f][h]
__device__ float g_w2t [(size_t)HID * EF];         //  67 MB W2^T [h][e*F+f]
__device__ float g_c1p [(size_t)NEXP * CAP * FFN]; // 138 MB compact act
__device__ float g_y   [(size_t)NEXP * CAP * HID]; //  35 MB compact y
__device__ int   g_idx [NEXP * CAP];               // expert -> token list
__device__ int   g_slot[T_TOK * NEXP];             // (t,e) -> slot
__device__ int   g_cnt [NEXP];

// ---------------------------------------------------------------------------
// helpers
// ---------------------------------------------------------------------------
__device__ __forceinline__ uint32_t smem_u32(const void* p) {
    uint32_t a;
    asm("{ .reg .u64 t; cvta.to.shared.u64 t, %1; cvt.u32.u64 %0, t; }"
        : "=r"(a) : "l"(p));
    return a;
}

__device__ __forceinline__ float to_tf32(float x) {
    uint32_t u;
    asm("cvt.rna.tf32.f32 %0, %1;" : "=r"(u) : "f"(x));
    return __uint_as_float(u);
}

__device__ __forceinline__ uint32_t sw128(uint32_t off) {
    return off ^ ((off >> 3) & 0x70);
}

__device__ __forceinline__ void cpa16(uint32_t dst, const void* src) {
    asm volatile("cp.async.cg.shared.global [%0], [%1], 16;"
                 :: "r"(dst), "l"(src) : "memory");
}

__device__ __forceinline__ void ldsm4(uint32_t* d, uint32_t addr) {
    asm volatile("ldmatrix.sync.aligned.m8n8.x4.shared.b16 {%0,%1,%2,%3}, [%4];"
                 : "=r"(d[0]), "=r"(d[1]), "=r"(d[2]), "=r"(d[3]) : "r"(addr));
}

__device__ __forceinline__ void mma8(float* c, const uint32_t* a,
                                     uint32_t b0, uint32_t b1) {
    asm volatile(
        "mma.sync.aligned.m16n8k8.row.col.f32.tf32.tf32.f32 "
        "{%0,%1,%2,%3}, {%4,%5,%6,%7}, {%8,%9}, {%0,%1,%2,%3};"
        : "+f"(c[0]), "+f"(c[1]), "+f"(c[2]), "+f"(c[3])
        : "r"(a[0]), "r"(a[1]), "r"(a[2]), "r"(a[3]), "r"(b0), "r"(b1));
}

__device__ __forceinline__ float gelu_exact(float x) {
    return 0.5f * x * (1.0f + erff(x * 0.70710678118654752f));
}

// ---------------------------------------------------------------------------
// pre-pass kernels
// ---------------------------------------------------------------------------
__global__ void round_tf32(const float* __restrict__ in, float* __restrict__ out,
                           int n4) {
    int i = blockIdx.x * 256 + threadIdx.x;
    if (i < n4) {
        float4 v = ((const float4*)in)[i];
        v.x = to_tf32(v.x); v.y = to_tf32(v.y);
        v.z = to_tf32(v.z); v.w = to_tf32(v.w);
        ((float4*)out)[i] = v;
    }
}

// in[b][r][c] -> out[b][c][r], rounded. 64x64 tiles, float4 both gmem sides.
__global__ void transpose_cvt(const float* __restrict__ in, float* __restrict__ out,
                              int R, int C) {
    __shared__ float tile[64][68];                 // [c][r]
    size_t base = (size_t)blockIdx.z * R * C;
    int c0 = blockIdx.x << 6, r0 = blockIdx.y << 6;
    int tx = threadIdx.x, ty = threadIdx.y;        // 16 x 16
    #pragma unroll
    for (int i = 0; i < 4; i++) {
        int rr = ty + (i << 4);
        float4 v = *(const float4*)&in[base + (size_t)(r0 + rr) * C + c0 + (tx << 2)];
        tile[(tx << 2) + 0][rr] = to_tf32(v.x);
        tile[(tx << 2) + 1][rr] = to_tf32(v.y);
        tile[(tx << 2) + 2][rr] = to_tf32(v.z);
        tile[(tx << 2) + 3][rr] = to_tf32(v.w);
    }
    __syncthreads();
    #pragma unroll
    for (int i = 0; i < 4; i++) {
        int cc = ty + (i << 4);
        float4 w = *(const float4*)&tile[cc][tx << 2];
        *(float4*)&out[base + (size_t)(c0 + cc) * R + r0 + (tx << 2)] = w;
    }
}

// zero counters + index list (every launch: graph replay must be stateless)
__global__ void route_zero(int* idx, int* cnt) {
    int i = blockIdx.x * 256 + threadIdx.x;
    if (i < NEXP * CAP) idx[i] = 0;
    if (i < NEXP) cnt[i] = 0;
}

__global__ void route_build(const float* __restrict__ probs,
                            int* idx, int* slot, int* cnt) {
    int t = blockIdx.x * 256 + threadIdx.x;
    if (t >= T_TOK) return;
    #pragma unroll
    for (int e = 0; e < NEXP; e++) {
        if (probs[t * NEXP + e] > 0.0f) {
            int pos = atomicAdd(&cnt[e], 1);
            idx[e * CAP + pos] = t;
            slot[t * NEXP + e] = pos;
        }
    }
}

// combine: out[t] = resid[t] + sum_e (probs>0) y[e][slot]
__global__ void combine(const float* __restrict__ y,
                        const float* __restrict__ probs,
                        const int* __restrict__ slot,
                        const float* __restrict__ resid,
                        float* __restrict__ out) {
    int t = blockIdx.x;
    int j = threadIdx.x;                          // 256 -> float4 over HID
    float4 acc = ((const float4*)resid)[t * (HID / 4) + j];
    #pragma unroll
    for (int e = 0; e < NEXP; e++) {
        if (probs[t * NEXP + e] > 0.0f) {
            int s = slot[t * NEXP + e];
            float4 v = ((const float4*)y)[((size_t)e * CAP + s) * (HID / 4) + j];
            acc.x += v.x; acc.y += v.y; acc.z += v.z; acc.w += v.w;
        }
    }
    ((float4*)out)[t * (HID / 4) + j] = acc;
}

// ---------------------------------------------------------------------------
// Routed GEMM. CTA tile BMT x BNT, warp grid 2 x WNW (warp tile (BMT/2) x 64),
// BK=32, STAGES-deep cp.async pipeline with ONE barrier per chunk.
// gridDim.y = NEXP*TPE (expert-major); CTAs past cnt[e] exit.
// MODE 0 (fc1): A rows gathered via token list; epi gelu*probs -> c1p (tf32).
// MODE 1 (fc2): A compact c1p rows; epi plain store -> y.
// ---------------------------------------------------------------------------
template<int MODE, int BMT, int BNT, int WNW, int STAGES, int TPE, int OCC>
__global__ void __launch_bounds__(64 * WNW, OCC)
moe_gemm(const float* __restrict__ A,     // MODE0: g_xr [T,H]; MODE1: g_c1p
         const float* __restrict__ Bt,    // MODE0: g_w1t [EF][H]; MODE1: g_w2t [H][EF]
         const float* __restrict__ probs, // [T,E]
         const int* __restrict__ idx,
         const int* __restrict__ cnt,
         float* __restrict__ Cout,        // MODE0: g_c1p; MODE1: g_y
         int K)                           // MODE0: HID; MODE1: FFN
{
    constexpr int THREADS = 64 * WNW;
    constexpr int WM      = BMT / 2;      // warp tile M
    constexpr int MT      = WM / 16;
    constexpr int NT      = 8;            // warp tile N = 64
    constexpr int A_BYTES = BMT * 128;
    constexpr int B_BYTES = BNT * 128;
    constexpr int STAGE   = A_BYTES + B_BYTES;

    extern __shared__ __align__(128) char smem[];
    const uint32_t sb = smem_u32(smem);
    int* s_token = (int*)(smem + STAGES * STAGE);

    const int e    = blockIdx.y / TPE;
    const int tile = blockIdx.y % TPE;
    const int cnt_e = cnt[e];
    if (tile * BMT >= cnt_e) return;

    const int tid  = threadIdx.x;
    const int wid  = tid >> 5;
    const int lane = tid & 31;
    const int wm   = wid / WNW;           // 0..1
    const int wn   = wid % WNW;           // 0..WNW-1
    const int n0   = blockIdx.x * BNT;
    const int row_base = e * CAP + tile * BMT;

    if (MODE == 0) {
        for (int i = tid; i < BMT; i += THREADS) s_token[i] = idx[row_base + i];
    }
    __syncthreads();

    const int CCH = K / 32;

    auto issue = [&](int c, int s) {
        uint32_t dA = sb + (uint32_t)s * STAGE;
        uint32_t dB = dA + A_BYTES;
        const int k0 = c * 32;
        #pragma unroll
        for (int i = 0; i < BMT * 8 / THREADS; i++) {   // A: BMT rows x 2 x 16B
            int id2 = tid + i * THREADS;
            int row = id2 >> 3, cb = (id2 & 7) << 4;
            const float* asrc;
            if (MODE == 0)
                asrc = A + (size_t)s_token[row] * K + k0 + (cb >> 2);
            else
                asrc = A + (size_t)(row_base + row) * K + k0 + (cb >> 2);
            cpa16(dA + sw128((uint32_t)(row * 128 + cb)), asrc);
        }
        #pragma unroll
        for (int i = 0; i < BNT * 8 / THREADS; i++) {   // B: BNT rows K-contig
            int id2 = tid + i * THREADS;
            int row = id2 >> 3, cb = (id2 & 7) << 4;
            const float* bsrc;
            if (MODE == 0)   // w1t rows e*F + n, stride K (=HID)
                bsrc = Bt + (size_t)(e * FFN + n0 + row) * K + k0 + (cb >> 2);
            else             // w2t rows n (stride EF), expert cols e*F + k
                bsrc = Bt + (size_t)(n0 + row) * EF + e * FFN + k0 + (cb >> 2);
            cpa16(dB + sw128((uint32_t)(row * 128 + cb)), bsrc);
        }
    };

    // prologue: first STAGES-1 chunks
    #pragma unroll
    for (int s = 0; s < STAGES - 1; s++) {
        issue(s, s);
        asm volatile("cp.async.commit_group;" ::: "memory");
    }

    float acc[MT][NT][4];
    #pragma unroll
    for (int mt = 0; mt < MT; mt++)
        #pragma unroll
        for (int nt = 0; nt < NT; nt++)
            #pragma unroll
            for (int i = 0; i < 4; i++) acc[mt][nt][i] = 0.0f;

    const int g = lane >> 3, r = lane & 7;

    #pragma unroll 1
    for (int c = 0; c < CCH; c++) {
        // commits so far = STAGES-1 + c; allow STAGES-2 pending -> chunk c ready
        asm volatile("cp.async.wait_group %0;" :: "n"(STAGES - 2));
        __syncthreads();
        // issue into buffer (c-1)%STAGES — its last readers finished before the
        // barrier above. Always commit (empty groups keep the count uniform).
        if (c + STAGES - 1 < CCH) issue(c + STAGES - 1, (c + STAGES - 1) % STAGES);
        asm volatile("cp.async.commit_group;" ::: "memory");

        const uint32_t sA  = sb + (uint32_t)(c % STAGES) * STAGE;
        const uint32_t sBm = sA + A_BYTES;

        #pragma unroll
        for (int ks = 0; ks < 4; ks++) {
            uint32_t bf[NT * 2];
            #pragma unroll
            for (int p = 0; p < NT / 2; p++) {
                int brow = wn * 64 + p * 16 + ((g >> 1) << 3) + r;
                int bcol = ks * 32 + ((g & 1) << 4);
                ldsm4(&bf[4 * p], sBm + sw128((uint32_t)(brow * 128 + bcol)));
            }
            uint32_t af[2][4];
            {
                int arow = wm * WM + ((g & 1) << 3) + r;
                int acol = ks * 32 + ((g >> 1) << 4);
                ldsm4(af[0], sA + sw128((uint32_t)(arow * 128 + acol)));
            }
            #pragma unroll
            for (int mt = 0; mt < MT; mt++) {
                if (mt + 1 < MT) {
                    int arow = wm * WM + (mt + 1) * 16 + ((g & 1) << 3) + r;
                    int acol = ks * 32 + ((g >> 1) << 4);
                    ldsm4(af[(mt + 1) & 1], sA + sw128((uint32_t)(arow * 128 + acol)));
                }
                #pragma unroll
                for (int nt = 0; nt < NT; nt++)
                    mma8(acc[mt][nt], af[mt & 1], bf[nt * 2], bf[nt * 2 + 1]);
            }
        }
    }

    // ---------------- epilogue ----------------
    const int qr = lane >> 2, rm = lane & 3;
    const int ldc = (MODE == 0) ? FFN : HID;

    #pragma unroll
    for (int mt = 0; mt < MT; mt++) {
        const int lr0 = wm * WM + mt * 16 + qr;       // local compact row
        const int lr1 = lr0 + 8;
        float p0 = 1.0f, p1 = 1.0f;
        if (MODE == 0) {
            p0 = probs[s_token[lr0] * NEXP + e];
            p1 = probs[s_token[lr1] * NEXP + e];
        }
        #pragma unroll
        for (int nt = 0; nt < NT; nt++) {
            const int col = n0 + wn * 64 + nt * 8 + (rm << 1);
            float2 v0, v1;
            if (MODE == 0) {
                v0.x = to_tf32(gelu_exact(acc[mt][nt][0]) * p0);
                v0.y = to_tf32(gelu_exact(acc[mt][nt][1]) * p0);
                v1.x = to_tf32(gelu_exact(acc[mt][nt][2]) * p1);
                v1.y = to_tf32(gelu_exact(acc[mt][nt][3]) * p1);
            } else {
                v0.x = acc[mt][nt][0]; v0.y = acc[mt][nt][1];
                v1.x = acc[mt][nt][2]; v1.y = acc[mt][nt][3];
            }
            *(float2*)&Cout[(size_t)(row_base + lr0) * ldc + col] = v0;
            *(float2*)&Cout[(size_t)(row_base + lr1) * ldc + col] = v1;
        }
    }
}

// ---------------------------------------------------------------------------
// launch
// ---------------------------------------------------------------------------
extern "C" void kernel_launch(void* const* d_in, const int* in_sizes, int n_in,
                              void* d_out, int out_size) {
    const float* x     = (const float*)d_in[0];   // hidden_states [T,H]
    const float* resid = (const float*)d_in[1];   // mlp_residual  [T,H]
    const float* probs = (const float*)d_in[2];   // probs [T,E] (masked)
    // d_in[3] = routing_map (unused: probs>0 is the same mask, dtype-safe)
    const float* w1    = (const float*)d_in[4];   // [E,H,F]
    const float* w2    = (const float*)d_in[5];   // [E,F,H]
    float* out = (float*)d_out;

    float *xr, *w1t, *w2t, *c1p, *yp;
    int *idxp, *slotp, *cntp;
    cudaGetSymbolAddress((void**)&xr,   g_xr);
    cudaGetSymbolAddress((void**)&w1t,  g_w1t);
    cudaGetSymbolAddress((void**)&w2t,  g_w2t);
    cudaGetSymbolAddress((void**)&c1p,  g_c1p);
    cudaGetSymbolAddress((void**)&yp,   g_y);
    cudaGetSymbolAddress((void**)&idxp, g_idx);
    cudaGetSymbolAddress((void**)&slotp, g_slot);
    cudaGetSymbolAddress((void**)&cntp, g_cnt);

    // GEMM1: 192x256, 2x4 warps, 3-stage, 1 CTA/SM
    constexpr int SMEM1 = 3 * (192 * 128 + 256 * 128) + 192 * 4;   // 172800
    // GEMM2: 96x128, 2x2 warps, 2-stage, occupancy 3
    constexpr int SMEM2 = 2 * (96 * 128 + 128 * 128) + 96 * 4;     // 57728

    auto* k1 = moe_gemm<0, 192, 256, 4, 3, 11, 1>;
    auto* k2 = moe_gemm<1,  96, 128, 2, 2, 22, 3>;
    cudaFuncSetAttribute(k1, cudaFuncAttributeMaxDynamicSharedMemorySize, SMEM1);
    cudaFuncSetAttribute(k2, cudaFuncAttributeMaxDynamicSharedMemorySize, SMEM2);

    // routing
    route_zero<<<(NEXP * CAP + 255) / 256, 256>>>(idxp, cntp);
    route_build<<<(T_TOK + 255) / 256, 256>>>(probs, idxp, slotp, cntp);

    // operand prep: round X; transpose+round W1 -> [EF][H], W2 -> [H][EF]
    round_tf32<<<(T_TOK * HID / 4 + 255) / 256, 256>>>(x, xr, T_TOK * HID / 4);
    transpose_cvt<<<dim3(FFN / 64, HID / 64, NEXP), dim3(16, 16)>>>(w1, w1t, HID, FFN);
    transpose_cvt<<<dim3(HID / 64, EF / 64, 1),    dim3(16, 16)>>>(w2, w2t, EF, HID);

    // routed GEMM1: gather X -> gelu*probs -> c1p.   grid (16, 44) x 256T
    k1<<<dim3(FFN / 256, NEXP * 11), 256, SMEM1>>>(
        xr, w1t, probs, idxp, cntp, c1p, HID);
    // routed GEMM2: c1p @ W2[e] -> y.                grid (8, 88) x 128T
    k2<<<dim3(HID / 128, NEXP * 22), 128, SMEM2>>>(
        c1p, w2t, probs, idxp, cntp, yp, FFN);
    // combine: out = resid + sum_topk y
    combine<<<T_TOK, 256>>>(yp, probs, slotp, resid, out);
}